// round 17
// baseline (speedup 1.0000x reference)
#include <cuda_runtime.h>

// SFAM_43490838839386: f = clip(tanh(x)/||tanh(x)||_2 + 0.01*noise, -1.5, 1.5)
//                      out = tanh(einsum('bi,bij->bj', f, P))
// B=4096, D=256, S=256, fp32. HBM-bound: P = 1.07 GB read once.
// R16 = R15 resubmit (infra failure): R13 minus one barrier. Stage
// t=tanh(raw) and 0.01*noise in smem BEFORE the warp-sums barrier; consumers
// apply the norm+clamp inline in the stream loop. One barrier serves both
// the reduce and the staged arrays, so the P-stream starts a barrier earlier
// in every CTA.

#define Dk 256
#define Sk 256
#define NOISE_STD 0.01f
#define EPSN 1e-12f

__global__ __launch_bounds__(256, 8)
void sfam_kernel(const float* __restrict__ raw,
                 const float* __restrict__ proj,
                 const float* __restrict__ noise,
                 float* __restrict__ out)
{
    __shared__ float t_sh[Dk];          // tanh(raw), pre-norm
    __shared__ float n_sh[Dk];          // 0.01 * noise
    __shared__ float red[8 * 128];
    __shared__ float warp_sums[8];

    const int b    = blockIdx.x >> 1;   // sample
    const int half = blockIdx.x & 1;    // which 128-column half
    const int tid  = threadIdx.x;

    // ---------------- Phase 1 (single barrier) -------------------------------
    const float rawv   = raw  [(size_t)b * Dk + tid];   // warm-L2 hits
    const float noisev = noise[(size_t)b * Dk + tid];

    const float t = tanhf(rawv);
    t_sh[tid] = t;                       // staged BEFORE the barrier
    n_sh[tid] = NOISE_STD * noisev;

    float sq = t * t;
    #pragma unroll
    for (int o = 16; o > 0; o >>= 1)
        sq += __shfl_xor_sync(0xffffffffu, sq, o);
    if ((tid & 31) == 0) warp_sums[tid >> 5] = sq;
    __syncthreads();                     // publishes warp_sums AND t_sh/n_sh

    float nrm = 0.f;
    #pragma unroll
    for (int w = 0; w < 8; w++) nrm += warp_sums[w];
    const float inv = 1.0f / fmaxf(sqrtf(nrm), EPSN);

    // ---------------- Phase 2: hashed[j] = sum_i f[i] * P[b,i,j] -------------
    // f[i] materialized inline: clamp(t_sh[i]*inv + n_sh[i]). 32 float4 column
    // groups x 8 i-slices; warp covers 512B contiguous per row (coalesced).
    const int jg     = tid & 31;
    const int islice = tid >> 5;

    const float* pbase = proj + (size_t)b * Dk * Sk + (size_t)half * 128 + (size_t)jg * 4;
    float4 acc = make_float4(0.f, 0.f, 0.f, 0.f);

    #pragma unroll 8
    for (int i = islice; i < Dk; i += 8) {
        const float  fi = fminf(fmaxf(fmaf(t_sh[i], inv, n_sh[i]), -1.5f), 1.5f);
        const float4 p  = __ldcs(reinterpret_cast<const float4*>(pbase + (size_t)i * Sk));
        acc.x = fmaf(fi, p.x, acc.x);
        acc.y = fmaf(fi, p.y, acc.y);
        acc.z = fmaf(fi, p.z, acc.z);
        acc.w = fmaf(fi, p.w, acc.w);
    }

    *reinterpret_cast<float4*>(&red[islice * 128 + jg * 4]) = acc;
    __syncthreads();

    // Reduce 8 slices per column, final tanh, streaming store.
    if (tid < 128) {
        float h = 0.f;
        #pragma unroll
        for (int s = 0; s < 8; s++) h += red[s * 128 + tid];
        __stcs(&out[(size_t)b * Sk + (size_t)half * 128 + tid], tanhf(h));
    }
}

extern "C" void kernel_launch(void* const* d_in, const int* in_sizes, int n_in,
                              void* d_out, int out_size)
{
    const float* raw   = (const float*)d_in[0];
    const float* proj  = (const float*)d_in[1];
    const float* noise = (const float*)d_in[2];
    float* out = (float*)d_out;

    const int B = in_sizes[0] / Dk;  // 4096
    sfam_kernel<<<2 * B, 256>>>(raw, proj, noise, out);
}